// round 3
// baseline (speedup 1.0000x reference)
#include <cuda_runtime.h>
#include <math.h>
#include <stdint.h>

#define N_  50000
#define T_  1000
#define KL  5
#define KR  15
#define NC  5
#define TWO_PI_F 6.28318530717958647692f
#define NPART 196

// ---------------- device scratch (no allocations allowed) ----------------
__device__ float g_part[NPART * 72];     // per-block partials: [cnt 5 | amp 20 | cos 20 | sin 20]
__device__ float g_cnt[NC];
__device__ float g_amp_mean[4 * NC];
__device__ float g_ph_mean[4 * NC];
__device__ float g_coef2[N_ * 20];       // duplicated coeff pairs per row:
                                         // (off,off)(tr,tr)(A0,A0)..(A3,A3)(B0,B0)..(B3,B3)

// ---------------- f32x2 packed helpers ----------------
__device__ __forceinline__ uint64_t pack2(float x, float y) {
    uint64_t d;
    asm("mov.b64 %0, {%1, %2};" : "=l"(d) : "f"(x), "f"(y));
    return d;
}
__device__ __forceinline__ uint64_t ffma2(uint64_t a, uint64_t b, uint64_t c) {
    uint64_t d;
    asm("fma.rn.f32x2 %0, %1, %2, %3;" : "=l"(d) : "l"(a), "l"(b), "l"(c));
    return d;
}

// ---------------- kernel 1: per-block cluster partial sums ----------------
__global__ void __launch_bounds__(256) k_part(const float* __restrict__ amps,
                                              const float* __restrict__ phs,
                                              const int* __restrict__ labels, int n) {
    __shared__ float s[65];  // cnt[5] | amp[20] | cos[20] | sin[20]
    int tid = threadIdx.x;
    if (tid < 65) s[tid] = 0.f;
    __syncthreads();

    int idx = blockIdx.x * blockDim.x + tid;
    if (idx < n) {
        int lab = labels[idx];
        atomicAdd(&s[lab], 1.f);
        float4 a = ((const float4*)amps)[idx];
        float4 p = ((const float4*)phs)[idx];
        float av[4] = {a.x, a.y, a.z, a.w};
        float pv[4] = {p.x, p.y, p.z, p.w};
#pragma unroll
        for (int i = 0; i < 4; i++) {
            atomicAdd(&s[5 + i * NC + lab], av[i]);
            float sv, cv;
            sincosf(pv[i], &sv, &cv);
            atomicAdd(&s[25 + i * NC + lab], cv);
            atomicAdd(&s[45 + i * NC + lab], sv);
        }
    }
    __syncthreads();
    if (tid < 65) g_part[blockIdx.x * 72 + tid] = s[tid];
}

// ---------------- kernel 2: reduce partials -> cluster means ----------------
// 256 threads: thread layout (i, b4) — each of 4 thread-groups sums a strided
// quarter of the 196 partials for its slot, then a tiny cross-group add.
__global__ void __launch_bounds__(256) k_final() {
    __shared__ float s[65][4];
    int t = threadIdx.x;
    int slot = t & 63;       // 0..63 covers slots 0..64 via extra pass below
    int grp  = t >> 6;       // 0..3
    // two passes of slots (0..63, then 64)
    for (int pass = 0; pass < 2; pass++) {
        int sl = slot + pass * 64;
        if (sl < 65) {
            float acc = 0.f;
            for (int b = grp; b < NPART; b += 4) acc += g_part[b * 72 + sl];
            s[sl][grp] = acc;
        }
    }
    __syncthreads();
    if (t < 65) {
        float v = s[t][0] + s[t][1] + s[t][2] + s[t][3];
        s[t][0] = v;
    }
    __syncthreads();
    if (t < NC) g_cnt[t] = s[t][0];
    if (t < 4 * NC) {
        int c = t % NC;
        g_amp_mean[t] = s[5 + t][0] / fmaxf(s[c][0], 1.f);
        g_ph_mean[t]  = atan2f(s[45 + t][0], s[25 + t][0]);
    }
}

// ---------------- kernel 3: spatial message passing -> duplicated coefficients ----------------
__global__ void __launch_bounds__(256) k_mp(const float* __restrict__ amps,
                                            const float* __restrict__ phs,
                                            const float* __restrict__ lw,
                                            const float* __restrict__ rw,
                                            const int* __restrict__ lidx,
                                            const int* __restrict__ ridx,
                                            const int* __restrict__ labels,
                                            const float* __restrict__ coff,
                                            const float* __restrict__ ctr) {
    int n = blockIdx.x * blockDim.x + threadIdx.x;
    if (n >= N_) return;

    float4 pa4 = ((const float4*)amps)[n];
    float4 pp4 = ((const float4*)phs)[n];
    float pa[4] = {pa4.x, pa4.y, pa4.z, pa4.w};
    float pp[4] = {pp4.x, pp4.y, pp4.z, pp4.w};

    float la[4] = {0, 0, 0, 0}, lc[4] = {0, 0, 0, 0}, ls[4] = {0, 0, 0, 0};
    float ra[4] = {0, 0, 0, 0}, rc[4] = {0, 0, 0, 0}, rs[4] = {0, 0, 0, 0};

#pragma unroll
    for (int k = 0; k < KL; k++) {
        int j = lidx[n * KL + k];
        float w = lw[n * KL + k];
        float4 a = ((const float4*)amps)[j];
        float4 p = ((const float4*)phs)[j];
        float av[4] = {a.x, a.y, a.z, a.w};
        float pv[4] = {p.x, p.y, p.z, p.w};
#pragma unroll
        for (int i = 0; i < 4; i++) {
            la[i] = fmaf(av[i], w, la[i]);
            float sv, cv;
            sincosf(pv[i], &sv, &cv);
            lc[i] = fmaf(cv, w, lc[i]);
            ls[i] = fmaf(sv, w, ls[i]);
        }
    }
#pragma unroll
    for (int k = 0; k < KR; k++) {
        int j = ridx[n * KR + k];
        float w = rw[n * KR + k];
        float4 a = ((const float4*)amps)[j];
        float4 p = ((const float4*)phs)[j];
        float av[4] = {a.x, a.y, a.z, a.w};
        float pv[4] = {p.x, p.y, p.z, p.w};
#pragma unroll
        for (int i = 0; i < 4; i++) {
            ra[i] = fmaf(av[i], w, ra[i]);
            float sv, cv;
            sincosf(pv[i], &sv, &cv);
            rc[i] = fmaf(cv, w, rc[i]);
            rs[i] = fmaf(sv, w, rs[i]);
        }
    }

    int lab = labels[n];
    bool useClu = g_cnt[lab] > 1.f;

    float A[4], B[4];
#pragma unroll
    for (int i = 0; i < 4; i++) {
        // amplitude (is_phase = false)
        float amp_cu = useClu ? g_amp_mean[i * NC + lab] : pa[i];
        float combA = 0.5f * la[i] + 0.3f * (ra[i] * 0.7f) + 0.2f * amp_cu;
        float ampf = 0.7f * pa[i] + 0.3f * combA;
        // phase (is_phase = true)
        float ph_lu = atan2f(ls[i], lc[i]);
        float ph_ru = atan2f(rs[i], rc[i]);
        float ph_cu = useClu ? g_ph_mean[i * NC + lab] : pp[i];
        float combP = 0.5f * ph_lu + 0.3f * ph_ru + 0.2f * ph_cu;
        float phf = 0.7f * pp[i] + 0.3f * combP;

        float sv, cv;
        sincosf(phf, &sv, &cv);
        A[i] = ampf * cv;  // multiplies sin(w t)
        B[i] = ampf * sv;  // multiplies cos(w t)
    }

    float off = coff[n];
    float tr  = ctr[n];
    float4* dst = (float4*)&g_coef2[n * 20];
    dst[0] = make_float4(off,  off,  tr,   tr);
    dst[1] = make_float4(A[0], A[0], A[1], A[1]);
    dst[2] = make_float4(A[2], A[2], A[3], A[3]);
    dst[3] = make_float4(B[0], B[0], B[1], B[1]);
    dst[4] = make_float4(B[2], B[2], B[3], B[3]);
}

// ---------------- kernel 4: signal generation (packed f32x2 FMAs) ----------------
// Each thread owns 4 fixed t-columns (2 f32x2 pairs); trig basis lives in registers.
// Per row per thread: 5 x LDG.128 (uniform, L1-hit) + 18 FFMA2 + 1 STG.128.
__global__ void __launch_bounds__(256) k_gen(const float* __restrict__ timev,
                                             float* __restrict__ out) {
    int tid = threadIdx.x;
    int t0 = tid * 4;
    if (t0 >= T_) return;

    float4 tv = *(const float4*)(timev + t0);
    uint64_t tv01 = pack2(tv.x, tv.y);
    uint64_t tv23 = pack2(tv.z, tv.w);

    const float freqs[4] = {4.f, 2.f, 1.f, 0.5f};
    uint64_t sb01[4], sb23[4], cb01[4], cb23[4];
#pragma unroll
    for (int i = 0; i < 4; i++) {
        float w = TWO_PI_F * freqs[i];
        float s0, c0, s1, c1, s2, c2, s3, c3;
        sincosf(w * tv.x, &s0, &c0);
        sincosf(w * tv.y, &s1, &c1);
        sincosf(w * tv.z, &s2, &c2);
        sincosf(w * tv.w, &s3, &c3);
        sb01[i] = pack2(s0, s1);
        sb23[i] = pack2(s2, s3);
        cb01[i] = pack2(c0, c1);
        cb23[i] = pack2(c2, c3);
    }

#pragma unroll 2
    for (int n = blockIdx.x; n < N_; n += gridDim.x) {
        const ulonglong2* cf = (const ulonglong2*)(g_coef2 + n * 20);
        ulonglong2 v0 = __ldg(cf + 0);  // (off2, tr2)
        ulonglong2 v1 = __ldg(cf + 1);  // (A0_2, A1_2)
        ulonglong2 v2 = __ldg(cf + 2);  // (A2_2, A3_2)
        ulonglong2 v3 = __ldg(cf + 3);  // (B0_2, B1_2)
        ulonglong2 v4 = __ldg(cf + 4);  // (B2_2, B3_2)

        uint64_t a01 = ffma2(v0.y, tv01, v0.x);
        uint64_t a23 = ffma2(v0.y, tv23, v0.x);

        a01 = ffma2(v1.x, sb01[0], a01);  a23 = ffma2(v1.x, sb23[0], a23);
        a01 = ffma2(v1.y, sb01[1], a01);  a23 = ffma2(v1.y, sb23[1], a23);
        a01 = ffma2(v2.x, sb01[2], a01);  a23 = ffma2(v2.x, sb23[2], a23);
        a01 = ffma2(v2.y, sb01[3], a01);  a23 = ffma2(v2.y, sb23[3], a23);
        a01 = ffma2(v3.x, cb01[0], a01);  a23 = ffma2(v3.x, cb23[0], a23);
        a01 = ffma2(v3.y, cb01[1], a01);  a23 = ffma2(v3.y, cb23[1], a23);
        a01 = ffma2(v4.x, cb01[2], a01);  a23 = ffma2(v4.x, cb23[2], a23);
        a01 = ffma2(v4.y, cb01[3], a01);  a23 = ffma2(v4.y, cb23[3], a23);

        float* dst = out + (size_t)n * T_ + t0;
        asm volatile("st.global.v2.u64 [%0], {%1, %2};"
                     :: "l"(dst), "l"(a01), "l"(a23) : "memory");
    }
}

// ---------------- launch ----------------
extern "C" void kernel_launch(void* const* d_in, const int* in_sizes, int n_in,
                              void* d_out, int out_size) {
    const float* timev  = (const float*)d_in[0];
    const float* coff   = (const float*)d_in[1];
    const float* ctr    = (const float*)d_in[2];
    const float* amps   = (const float*)d_in[3];
    const float* phs    = (const float*)d_in[4];
    const float* lw     = (const float*)d_in[5];
    const float* rw     = (const float*)d_in[6];
    const int*   lidx   = (const int*)d_in[7];
    const int*   ridx   = (const int*)d_in[8];
    const int*   labels = (const int*)d_in[9];
    float* out = (float*)d_out;

    int n = in_sizes[1];  // N = 50000

    k_part<<<NPART, 256>>>(amps, phs, labels, n);
    k_final<<<1, 256>>>();
    k_mp<<<(n + 255) / 256, 256>>>(amps, phs, lw, rw, lidx, ridx, labels, coff, ctr);
    k_gen<<<888, 256>>>(timev, out);
}